// round 1
// baseline (speedup 1.0000x reference)
#include <cuda_runtime.h>
#include <math.h>

#define NSEG 16
#define THREADS 256
#define V4_PER_THREAD 4

// Exact piecewise-quadratic eval:
//   est  = floor( (log2-ish(x) - offset) / w - margin )   in {idx-1, idx}, via int bit trick
//   est += (x > breaks[est+1])                             exact searchsorted-left correction
//   out  = (a*x + b)*x + c                                 coeffs from padded smem table
__global__ void __launch_bounds__(THREADS) piecewise_invsqrt_kernel(
    const float* __restrict__ xin,
    const float* __restrict__ breaks,
    const float* __restrict__ coeffs,
    float* __restrict__ out,
    int n, int n4, int full_blocks, int B0, int M)
{
    __shared__ int    s_bk[NSEG + 1];   // s_bk[j] = bits(breaks[j]), j = 0..16
    __shared__ float4 s_cf[NSEG + 1];   // s_cf[j] = coeffs[max(j-1,0)]  (slot 0 dups seg 0)

    int t = threadIdx.x;
    if (t <= NSEG) {
        s_bk[t] = __float_as_int(breaks[t]);
        int seg = (t == 0) ? 0 : (t - 1);
        s_cf[t] = make_float4(coeffs[seg * 3 + 0], coeffs[seg * 3 + 1],
                              coeffs[seg * 3 + 2], 0.0f);
    }
    __syncthreads();

    const long long Ml = (long long)M;

    auto eval = [&](float xv) -> float {
        int b   = __float_as_int(xv);
        int est = (int)(((long long)(b - B0) * Ml) >> 40);   // in {idx-1, idx}
        est += (b > s_bk[est + 1]) ? 1 : 0;                  // exact; est in [-1, 15]
        float4 c = s_cf[est + 1];
        return fmaf(fmaf(c.x, xv, c.y), xv, c.z);
    };

    const float4* in4  = (const float4*)xin;
    float4*       out4 = (float4*)out;

    if (blockIdx.x < full_blocks) {
        int base = blockIdx.x * (THREADS * V4_PER_THREAD) + t;
        float4 v[V4_PER_THREAD];
#pragma unroll
        for (int k = 0; k < V4_PER_THREAD; k++)
            v[k] = in4[base + k * THREADS];
#pragma unroll
        for (int k = 0; k < V4_PER_THREAD; k++) {
            float4 r;
            r.x = eval(v[k].x);
            r.y = eval(v[k].y);
            r.z = eval(v[k].z);
            r.w = eval(v[k].w);
            out4[base + k * THREADS] = r;
        }
    } else {
        // Tail block: leftover float4s, then scalar remainder (n % 4).
        int start = full_blocks * (THREADS * V4_PER_THREAD);
        for (int i = start + t; i < n4; i += THREADS) {
            float4 v = in4[i];
            float4 r;
            r.x = eval(v.x); r.y = eval(v.y); r.z = eval(v.z); r.w = eval(v.w);
            out4[i] = r;
        }
        for (int i = n4 * 4 + t; i < n; i += THREADS)
            out[i] = eval(xin[i]);
    }
}

extern "C" void kernel_launch(void* const* d_in, const int* in_sizes, int n_in,
                              void* d_out, int out_size)
{
    const float* x      = (const float*)d_in[0];
    const float* breaks = (const float*)d_in[1];
    const float* coeffs = (const float*)d_in[2];
    float*       out    = (float*)d_out;
    int n  = in_sizes[0];
    int n4 = n / 4;

    // Constants for the bits->segment estimate (double precision on host).
    // est_arg(bits) = (bits - B0) * M / 2^40
    //              = (log2(x) - eps(x) - log2(LO)) / w - 0.02
    // eps(x)/w in [0, 0.1295]  =>  est_arg in (pos_true - 1, pos_true)  => est in {idx-1, idx}
    const double LO = 0.01, HI = 16.0;
    double w     = log2(HI / LO) / (double)NSEG;           // 0.66524...
    double kk    = 1.0 / (8388608.0 * w);                  // per-bit slope
    double two40 = 1099511627776.0;                        // 2^40
    int    M     = (int)llround(kk * two40);               // ~197030
    double tt    = (127.0 + log2(LO)) / w + 0.02;          // offset + margin
    int    B0    = (int)llround(tt * two40 / (double)M);   // ~1.0097e9

    int per_block   = THREADS * V4_PER_THREAD;
    int full_blocks = n4 / per_block;
    int blocks      = full_blocks;
    if ((n4 % per_block) != 0 || (n % 4) != 0 || blocks == 0)
        blocks += 1;  // one tail block

    piecewise_invsqrt_kernel<<<blocks, THREADS>>>(x, breaks, coeffs, out,
                                                  n, n4, full_blocks, B0, M);
}

// round 2
// speedup vs baseline: 1.0018x; 1.0018x over previous
#include <cuda_runtime.h>
#include <math.h>

#define NSEG 16
#define THREADS 256
#define V4_PER_THREAD 4

// Exact piecewise-quadratic eval:
//   est  = floor( (log2-ish(x) - offset) / w - margin )   in {idx-1, idx}, via int bit trick
//   est += (x > breaks[est+1])                             exact searchsorted-left correction
//   out  = (a*x + b)*x + c                                 coeffs from padded smem table
// Streaming workload (1.07 GB, zero reuse): evict-first hints on both loads and stores.
__global__ void __launch_bounds__(THREADS) piecewise_invsqrt_kernel(
    const float* __restrict__ xin,
    const float* __restrict__ breaks,
    const float* __restrict__ coeffs,
    float* __restrict__ out,
    int n, int n4, int full_blocks, int B0, int M)
{
    __shared__ int    s_bk[NSEG + 1];   // s_bk[j] = bits(breaks[j]), j = 0..16
    __shared__ float4 s_cf[NSEG + 1];   // s_cf[j] = coeffs[max(j-1,0)]  (slot 0 dups seg 0)

    int t = threadIdx.x;
    if (t <= NSEG) {
        s_bk[t] = __float_as_int(breaks[t]);
        int seg = (t == 0) ? 0 : (t - 1);
        s_cf[t] = make_float4(coeffs[seg * 3 + 0], coeffs[seg * 3 + 1],
                              coeffs[seg * 3 + 2], 0.0f);
    }
    __syncthreads();

    const long long Ml  = (long long)M;
    const int*    bk1 = s_bk + 1;   // pre-biased: bk1[est] == s_bk[est+1]
    const float4* cf1 = s_cf + 1;   // pre-biased: cf1[est] == s_cf[est+1]

    auto eval = [&](float xv) -> float {
        int b   = __float_as_int(xv);
        int est = (int)(((long long)(b - B0) * Ml) >> 40);   // in {idx-1, idx}
        est += (b > bk1[est]) ? 1 : 0;                       // exact; est in [-1, 15]
        float4 c = cf1[est];
        return fmaf(fmaf(c.x, xv, c.y), xv, c.z);
    };

    const float4* in4  = (const float4*)xin;
    float4*       out4 = (float4*)out;

    if (blockIdx.x < full_blocks) {
        int base = blockIdx.x * (THREADS * V4_PER_THREAD) + t;
        float4 v[V4_PER_THREAD];
#pragma unroll
        for (int k = 0; k < V4_PER_THREAD; k++)
            v[k] = __ldcs(&in4[base + k * THREADS]);         // evict-first load
#pragma unroll
        for (int k = 0; k < V4_PER_THREAD; k++) {
            float4 r;
            r.x = eval(v[k].x);
            r.y = eval(v[k].y);
            r.z = eval(v[k].z);
            r.w = eval(v[k].w);
            __stcs(&out4[base + k * THREADS], r);            // evict-first store
        }
    } else {
        // Tail block: leftover float4s, then scalar remainder (n % 4).
        int start = full_blocks * (THREADS * V4_PER_THREAD);
        for (int i = start + t; i < n4; i += THREADS) {
            float4 v = __ldcs(&in4[i]);
            float4 r;
            r.x = eval(v.x); r.y = eval(v.y); r.z = eval(v.z); r.w = eval(v.w);
            __stcs(&out4[i], r);
        }
        for (int i = n4 * 4 + t; i < n; i += THREADS)
            out[i] = eval(xin[i]);
    }
}

extern "C" void kernel_launch(void* const* d_in, const int* in_sizes, int n_in,
                              void* d_out, int out_size)
{
    const float* x      = (const float*)d_in[0];
    const float* breaks = (const float*)d_in[1];
    const float* coeffs = (const float*)d_in[2];
    float*       out    = (float*)d_out;
    int n  = in_sizes[0];
    int n4 = n / 4;

    // Constants for the bits->segment estimate (double precision on host).
    // est_arg(bits) = (bits - B0) * M / 2^40
    //              = (log2(x) - eps(x) - log2(LO)) / w - 0.02
    // eps(x)/w in [0, 0.1295]  =>  est_arg in (pos_true - 1, pos_true)  => est in {idx-1, idx}
    const double LO = 0.01, HI = 16.0;
    double w     = log2(HI / LO) / (double)NSEG;           // 0.66524...
    double kk    = 1.0 / (8388608.0 * w);                  // per-bit slope
    double two40 = 1099511627776.0;                        // 2^40
    int    M     = (int)llround(kk * two40);               // ~197030
    double tt    = (127.0 + log2(LO)) / w + 0.02;          // offset + margin
    int    B0    = (int)llround(tt * two40 / (double)M);   // ~1.0097e9

    int per_block   = THREADS * V4_PER_THREAD;
    int full_blocks = n4 / per_block;
    int blocks      = full_blocks;
    if ((n4 % per_block) != 0 || (n % 4) != 0 || blocks == 0)
        blocks += 1;  // one tail block

    piecewise_invsqrt_kernel<<<blocks, THREADS>>>(x, breaks, coeffs, out,
                                                  n, n4, full_blocks, B0, M);
}